// round 1
// baseline (speedup 1.0000x reference)
#include <cuda_runtime.h>

#define NB   100   // neighbors
#define NF   13    // features
#define TPB  128

__device__ __forceinline__ void jrot(float M[3][3], float V[3][3], int p, int q) {
    float apq = M[p][q];
    if (fabsf(apq) < 1e-20f) return;
    float theta = (M[q][q] - M[p][p]) * 0.5f / apq;
    float t = copysignf(1.0f, theta) / (fabsf(theta) + sqrtf(theta * theta + 1.0f));
    float c = rsqrtf(t * t + 1.0f);
    float s = t * c;
    float mpp = M[p][p], mqq = M[q][q];
    M[p][p] = mpp - t * apq;
    M[q][q] = mqq + t * apq;
    M[p][q] = 0.0f; M[q][p] = 0.0f;
    int r = 3 - p - q;
    float mrp = M[r][p], mrq = M[r][q];
    M[r][p] = c * mrp - s * mrq; M[p][r] = M[r][p];
    M[r][q] = s * mrp + c * mrq; M[q][r] = M[r][q];
#pragma unroll
    for (int i = 0; i < 3; i++) {
        float vip = V[i][p], viq = V[i][q];
        V[i][p] = c * vip - s * viq;
        V[i][q] = s * vip + c * viq;
    }
}

__global__ void __launch_bounds__(TPB) svd_align_kernel(
    const float* __restrict__ in,
    const float* __restrict__ pa,
    const float* __restrict__ pb,
    const float* __restrict__ pshift,
    float* __restrict__ out)
{
    __shared__ float sdat[NB * NF];
    __shared__ float sred[4][16];
    __shared__ float sRt[12];   // R row-major (9) then t (3)

    const int b   = blockIdx.x;
    const int tid = threadIdx.x;
    const float a     = pa[0];
    const float bbias = pb[0];
    const float shift = pshift[0];

    // ---- load batch row into SMEM (coalesced) ----
    const size_t base = (size_t)b * (NB * NF);
    for (int i = tid; i < NB * NF; i += TPB) sdat[i] = in[base + i];
    __syncthreads();

    // ---- per-neighbor partials: [w, w*v1(3), w*v2(3), w*v2_k*v1_j(9)] ----
    float acc[16];
#pragma unroll
    for (int k = 0; k < 16; k++) acc[k] = 0.0f;

    if (tid < NB) {
        const float* r = &sdat[tid * NF];
        float w = a * r[0] + bbias;
        w = (w > 0.0f ? w : 0.0f) + 1e-8f;
        float v1[3], v2[3];
#pragma unroll
        for (int k = 0; k < 3; k++) {
            v1[k] = r[1 + k] + r[7 + k]  * shift;
            v2[k] = r[4 + k] + r[10 + k] * shift;
        }
        acc[0] = w;
#pragma unroll
        for (int k = 0; k < 3; k++) { acc[1 + k] = w * v1[k]; acc[4 + k] = w * v2[k]; }
#pragma unroll
        for (int k = 0; k < 3; k++)
#pragma unroll
            for (int j = 0; j < 3; j++)
                acc[7 + k * 3 + j] = (w * v2[k]) * v1[j];
    }

    // ---- warp reduce then cross-warp via SMEM ----
#pragma unroll
    for (int k = 0; k < 16; k++) {
#pragma unroll
        for (int off = 16; off > 0; off >>= 1)
            acc[k] += __shfl_down_sync(0xffffffffu, acc[k], off);
    }
    const int wid = tid >> 5, lane = tid & 31;
    if (lane == 0) {
#pragma unroll
        for (int k = 0; k < 16; k++) sred[wid][k] = acc[k];
    }
    __syncthreads();

    if (tid == 0) {
        float f[16];
#pragma unroll
        for (int k = 0; k < 16; k++)
            f[k] = sred[0][k] + sred[1][k] + sred[2][k] + sred[3][k];

        const float inv_w = 1.0f / f[0];
        float v1c[3], v2c[3];
#pragma unroll
        for (int k = 0; k < 3; k++) { v1c[k] = f[1 + k] * inv_w; v2c[k] = f[4 + k] * inv_w; }

        // cov[k][j] = sum w*v2_k*v1_j  -  (sum w*v2_k)(sum w*v1_j)/sum w
        float A[3][3];
#pragma unroll
        for (int k = 0; k < 3; k++)
#pragma unroll
            for (int j = 0; j < 3; j++)
                A[k][j] = f[7 + k * 3 + j] - f[4 + k] * f[1 + j] * inv_w;

        // M = A^T A (symmetric)
        float M[3][3];
#pragma unroll
        for (int i = 0; i < 3; i++)
#pragma unroll
            for (int j = 0; j < 3; j++) {
                float s = 0.0f;
#pragma unroll
                for (int k = 0; k < 3; k++) s += A[k][i] * A[k][j];
                M[i][j] = s;
            }

        float V[3][3] = {{1,0,0},{0,1,0},{0,0,1}};
#pragma unroll
        for (int sweep = 0; sweep < 6; sweep++) {
            jrot(M, V, 0, 1);
            jrot(M, V, 0, 2);
            jrot(M, V, 1, 2);
        }

        // sort eigenvalues descending, permuting V columns (det correction
        // must land on the SMALLEST singular direction, matching jnp SVD order)
        float e[3] = { M[0][0], M[1][1], M[2][2] };
#pragma unroll
        for (int i = 0; i < 2; i++)
#pragma unroll
            for (int j = 0; j < 2 - i; j++) {
                if (e[j] < e[j + 1]) {
                    float te = e[j]; e[j] = e[j + 1]; e[j + 1] = te;
#pragma unroll
                    for (int r = 0; r < 3; r++) {
                        float tv = V[r][j]; V[r][j] = V[r][j + 1]; V[r][j + 1] = tv;
                    }
                }
            }

        // U columns: u0 = norm(A v0); u1 = norm(A v1 - (u0.Av1)u0); u2 = u0 x u1
        float U[3][3];
#pragma unroll
        for (int k = 0; k < 2; k++)
#pragma unroll
            for (int i = 0; i < 3; i++)
                U[i][k] = A[i][0] * V[0][k] + A[i][1] * V[1][k] + A[i][2] * V[2][k];

        float n0 = rsqrtf(U[0][0]*U[0][0] + U[1][0]*U[1][0] + U[2][0]*U[2][0] + 1e-30f);
#pragma unroll
        for (int i = 0; i < 3; i++) U[i][0] *= n0;
        float d01 = U[0][0]*U[0][1] + U[1][0]*U[1][1] + U[2][0]*U[2][1];
#pragma unroll
        for (int i = 0; i < 3; i++) U[i][1] -= d01 * U[i][0];
        float n1 = rsqrtf(U[0][1]*U[0][1] + U[1][1]*U[1][1] + U[2][1]*U[2][1] + 1e-30f);
#pragma unroll
        for (int i = 0; i < 3; i++) U[i][1] *= n1;
        U[0][2] = U[1][0]*U[2][1] - U[2][0]*U[1][1];
        U[1][2] = U[2][0]*U[0][1] - U[0][0]*U[2][1];
        U[2][2] = U[0][0]*U[1][1] - U[1][0]*U[0][1];

        // det(U) = +1 by construction; d3 = sign(det V)
        float detV =
            V[0][0] * (V[1][1]*V[2][2] - V[2][1]*V[1][2]) -
            V[0][1] * (V[1][0]*V[2][2] - V[2][0]*V[1][2]) +
            V[0][2] * (V[1][0]*V[2][1] - V[2][0]*V[1][1]);
        float d3 = (detV > 0.0f) ? 1.0f : -1.0f;

        // R = V diag(1,1,d3) U^T ;  t = v1c - R v2c
        float R[3][3];
#pragma unroll
        for (int i = 0; i < 3; i++)
#pragma unroll
            for (int j = 0; j < 3; j++)
                R[i][j] = V[i][0]*U[j][0] + V[i][1]*U[j][1] + d3 * V[i][2]*U[j][2];

#pragma unroll
        for (int i = 0; i < 3; i++) {
#pragma unroll
            for (int j = 0; j < 3; j++) sRt[i * 3 + j] = R[i][j];
            sRt[9 + i] = v1c[i] - (R[i][0]*v2c[0] + R[i][1]*v2c[1] + R[i][2]*v2c[2]);
        }
    }
    __syncthreads();

    // ---- apply R,t to xyz2 / R to norm2; coalesced 600-float write ----
    const size_t obase = (size_t)b * (NB * 6);
    for (int idx = tid; idx < NB * 6; idx += TPB) {
        int n = idx / 6;
        int c = idx - n * 6;
        const float* row = &sdat[n * NF];
        int ci = (c < 3) ? c : c - 3;
        int off = (c < 3) ? 4 : 10;   // xyz2 at cols 4..6, norm2 at cols 10..12
        float val = sRt[ci*3 + 0] * row[off + 0]
                  + sRt[ci*3 + 1] * row[off + 1]
                  + sRt[ci*3 + 2] * row[off + 2];
        if (c < 3) val += sRt[9 + ci];
        out[obase + idx] = val;
    }
}

extern "C" void kernel_launch(void* const* d_in, const int* in_sizes, int n_in,
                              void* d_out, int out_size) {
    const float* net   = (const float*)d_in[0];
    const float* a     = (const float*)d_in[1];
    const float* b     = (const float*)d_in[2];
    const float* shift = (const float*)d_in[3];
    float* out = (float*)d_out;

    int B = in_sizes[0] / (NB * NF);   // 100000
    svd_align_kernel<<<B, TPB>>>(net, a, b, shift, out);
}

// round 2
// speedup vs baseline: 1.5766x; 1.5766x over previous
#include <cuda_runtime.h>

#define NB    100   // neighbors
#define NF    13    // features
#define ROW4  (NB * NF / 4)      // 325 float4 per batch
#define WPB   4                  // warps per block
#define TPB   (WPB * 32)

__device__ __forceinline__ void jrot(float M[3][3], float V[3][3], int p, int q) {
    float apq = M[p][q];
    if (fabsf(apq) < 1e-20f) return;
    float theta = (M[q][q] - M[p][p]) * 0.5f / apq;
    float t = copysignf(1.0f, theta) / (fabsf(theta) + sqrtf(theta * theta + 1.0f));
    float c = rsqrtf(t * t + 1.0f);
    float s = t * c;
    float mpp = M[p][p], mqq = M[q][q];
    M[p][p] = mpp - t * apq;
    M[q][q] = mqq + t * apq;
    M[p][q] = 0.0f; M[q][p] = 0.0f;
    int r = 3 - p - q;
    float mrp = M[r][p], mrq = M[r][q];
    M[r][p] = c * mrp - s * mrq; M[p][r] = M[r][p];
    M[r][q] = s * mrp + c * mrq; M[q][r] = M[r][q];
#pragma unroll
    for (int i = 0; i < 3; i++) {
        float vip = V[i][p], viq = V[i][q];
        V[i][p] = c * vip - s * viq;
        V[i][q] = s * vip + c * viq;
    }
}

__global__ void __launch_bounds__(TPB) svd_align_kernel(
    const float* __restrict__ in,
    const float* __restrict__ pa,
    const float* __restrict__ pb,
    const float* __restrict__ pshift,
    float* __restrict__ out,
    int B)
{
    __shared__ float sdat[WPB][NB * NF];

    const int wid  = threadIdx.x >> 5;
    const int lane = threadIdx.x & 31;
    const int wb   = blockIdx.x * WPB + wid;   // batch handled by this warp
    if (wb >= B) return;

    const float a     = pa[0];
    const float bbias = pb[0];
    const float shift = pshift[0];

    float* sm = sdat[wid];

    // ---- stage batch row into SMEM: 325 float4, coalesced ----
    const float4* src = (const float4*)(in + (size_t)wb * (NB * NF));
    float4* dst = (float4*)sm;
#pragma unroll
    for (int i = 0; i < 11; i++) {
        int q = i * 32 + lane;
        if (q < ROW4) dst[q] = src[q];
    }
    __syncwarp();

    // ---- partials over 100 neighbors, 3-4 rows per lane ----
    // [w, w*v1(3), w*v2(3), w*v2_k*v1_j(9)]
    float acc[16];
#pragma unroll
    for (int k = 0; k < 16; k++) acc[k] = 0.0f;

#pragma unroll
    for (int c = 0; c < 4; c++) {
        int n = c * 32 + lane;
        if (n < NB) {
            const float* r = &sm[n * NF];
            float w = a * r[0] + bbias;
            w = (w > 0.0f ? w : 0.0f) + 1e-8f;
            float v1[3], v2[3], wv2[3];
#pragma unroll
            for (int k = 0; k < 3; k++) {
                v1[k] = fmaf(shift, r[7 + k],  r[1 + k]);
                v2[k] = fmaf(shift, r[10 + k], r[4 + k]);
            }
            acc[0] += w;
#pragma unroll
            for (int k = 0; k < 3; k++) {
                acc[1 + k] = fmaf(w, v1[k], acc[1 + k]);
                wv2[k]     = w * v2[k];
                acc[4 + k] += wv2[k];
            }
#pragma unroll
            for (int k = 0; k < 3; k++)
#pragma unroll
                for (int j = 0; j < 3; j++)
                    acc[7 + k * 3 + j] = fmaf(wv2[k], v1[j], acc[7 + k * 3 + j]);
        }
    }

    // ---- warp-only shuffle reduce (to lane 0) ----
#pragma unroll
    for (int k = 0; k < 16; k++) {
#pragma unroll
        for (int off = 16; off > 0; off >>= 1)
            acc[k] += __shfl_down_sync(0xffffffffu, acc[k], off);
    }

    // ---- lane 0: 3x3 weighted-Kabsch SVD ----
    float R00, R01, R02, R10, R11, R12, R20, R21, R22, t0, t1, t2;
    if (lane == 0) {
        const float inv_w = 1.0f / acc[0];
        float v1c[3], v2c[3];
#pragma unroll
        for (int k = 0; k < 3; k++) { v1c[k] = acc[1 + k] * inv_w; v2c[k] = acc[4 + k] * inv_w; }

        float A[3][3];
#pragma unroll
        for (int k = 0; k < 3; k++)
#pragma unroll
            for (int j = 0; j < 3; j++)
                A[k][j] = acc[7 + k * 3 + j] - acc[4 + k] * acc[1 + j] * inv_w;

        float M[3][3];
#pragma unroll
        for (int i = 0; i < 3; i++)
#pragma unroll
            for (int j = 0; j < 3; j++) {
                float s = 0.0f;
#pragma unroll
                for (int k = 0; k < 3; k++) s += A[k][i] * A[k][j];
                M[i][j] = s;
            }

        float V[3][3] = {{1,0,0},{0,1,0},{0,0,1}};
#pragma unroll
        for (int sweep = 0; sweep < 5; sweep++) {
            jrot(M, V, 0, 1);
            jrot(M, V, 0, 2);
            jrot(M, V, 1, 2);
        }

        // sort eigenvalues descending (det correction lands on smallest dir)
        float e[3] = { M[0][0], M[1][1], M[2][2] };
#pragma unroll
        for (int i = 0; i < 2; i++)
#pragma unroll
            for (int j = 0; j < 2 - i; j++) {
                if (e[j] < e[j + 1]) {
                    float te = e[j]; e[j] = e[j + 1]; e[j + 1] = te;
#pragma unroll
                    for (int r = 0; r < 3; r++) {
                        float tv = V[r][j]; V[r][j] = V[r][j + 1]; V[r][j + 1] = tv;
                    }
                }
            }

        float U[3][3];
#pragma unroll
        for (int k = 0; k < 2; k++)
#pragma unroll
            for (int i = 0; i < 3; i++)
                U[i][k] = A[i][0] * V[0][k] + A[i][1] * V[1][k] + A[i][2] * V[2][k];

        float n0 = rsqrtf(U[0][0]*U[0][0] + U[1][0]*U[1][0] + U[2][0]*U[2][0] + 1e-30f);
#pragma unroll
        for (int i = 0; i < 3; i++) U[i][0] *= n0;
        float d01 = U[0][0]*U[0][1] + U[1][0]*U[1][1] + U[2][0]*U[2][1];
#pragma unroll
        for (int i = 0; i < 3; i++) U[i][1] -= d01 * U[i][0];
        float n1 = rsqrtf(U[0][1]*U[0][1] + U[1][1]*U[1][1] + U[2][1]*U[2][1] + 1e-30f);
#pragma unroll
        for (int i = 0; i < 3; i++) U[i][1] *= n1;
        U[0][2] = U[1][0]*U[2][1] - U[2][0]*U[1][1];
        U[1][2] = U[2][0]*U[0][1] - U[0][0]*U[2][1];
        U[2][2] = U[0][0]*U[1][1] - U[1][0]*U[0][1];

        float detV =
            V[0][0] * (V[1][1]*V[2][2] - V[2][1]*V[1][2]) -
            V[0][1] * (V[1][0]*V[2][2] - V[2][0]*V[1][2]) +
            V[0][2] * (V[1][0]*V[2][1] - V[2][0]*V[1][1]);
        float d3 = (detV > 0.0f) ? 1.0f : -1.0f;

        float R[3][3];
#pragma unroll
        for (int i = 0; i < 3; i++)
#pragma unroll
            for (int j = 0; j < 3; j++)
                R[i][j] = V[i][0]*U[j][0] + V[i][1]*U[j][1] + d3 * V[i][2]*U[j][2];

        R00 = R[0][0]; R01 = R[0][1]; R02 = R[0][2];
        R10 = R[1][0]; R11 = R[1][1]; R12 = R[1][2];
        R20 = R[2][0]; R21 = R[2][1]; R22 = R[2][2];
        t0 = v1c[0] - (R[0][0]*v2c[0] + R[0][1]*v2c[1] + R[0][2]*v2c[2]);
        t1 = v1c[1] - (R[1][0]*v2c[0] + R[1][1]*v2c[1] + R[1][2]*v2c[2]);
        t2 = v1c[2] - (R[2][0]*v2c[0] + R[2][1]*v2c[1] + R[2][2]*v2c[2]);
    }

    // broadcast R, t to all lanes
    float Rt[12];
    Rt[0]=R00; Rt[1]=R01; Rt[2]=R02; Rt[3]=R10; Rt[4]=R11; Rt[5]=R12;
    Rt[6]=R20; Rt[7]=R21; Rt[8]=R22; Rt[9]=t0; Rt[10]=t1; Rt[11]=t2;
#pragma unroll
    for (int k = 0; k < 12; k++) Rt[k] = __shfl_sync(0xffffffffu, Rt[k], 0);

    // ---- apply: 600 outputs as 150 float4, coalesced STG.128 ----
    float* ob = out + (size_t)wb * (NB * 6);
#pragma unroll
    for (int it = 0; it < 5; it++) {
        int q = it * 32 + lane;          // float4 index, < 150
        if (q < 150) {
            float4 o;
            float* op = (float*)&o;
#pragma unroll
            for (int s = 0; s < 4; s++) {
                int e = q * 4 + s;       // output element index < 600
                int n = e / 6;
                int c = e - n * 6;
                int ci  = (c < 3) ? c : c - 3;
                int off = (c < 3) ? 4 : 10;
                const float* row = &sm[n * NF];
                float val = Rt[ci*3 + 0] * row[off + 0]
                          + Rt[ci*3 + 1] * row[off + 1]
                          + Rt[ci*3 + 2] * row[off + 2];
                if (c < 3) val += Rt[9 + ci];
                op[s] = val;
            }
            ((float4*)ob)[q] = o;
        }
    }
}

extern "C" void kernel_launch(void* const* d_in, const int* in_sizes, int n_in,
                              void* d_out, int out_size) {
    const float* net   = (const float*)d_in[0];
    const float* a     = (const float*)d_in[1];
    const float* b     = (const float*)d_in[2];
    const float* shift = (const float*)d_in[3];
    float* out = (float*)d_out;

    int B = in_sizes[0] / (NB * NF);   // 100000
    int grid = (B + WPB - 1) / WPB;
    svd_align_kernel<<<grid, TPB>>>(net, a, b, shift, out, B);
}